// round 5
// baseline (speedup 1.0000x reference)
#include <cuda_runtime.h>

// Problem constants
constexpr int Bb   = 4;
constexpr int Ts   = 2048;
constexpr int Cc   = 1024;
constexpr int Hh   = 16;
constexpr int Dh   = 64;
constexpr int Mtot = Bb * Ts;      // 8192 rows
constexpr int Nqkv = 3 * Cc;       // 3072

// Scratch (device globals are the sanctioned scratch mechanism; no runtime allocs)
__device__ float g_qkv[(size_t)Mtot * Nqkv];   // 96 MB: [b*T+t][3*C] = [.., sel*C + h*Dh + d]
__device__ float g_att[(size_t)Mtot * Cc];     // 32 MB: [b*T+t][h*Dh + d]

// ---------------------------------------------------------------------------
// SGEMM: C[M,N] = A[M,K] @ B[K,N] + bias[N]
// 128x128 block tile, BK=8, 8x8 per-thread microtile, 256 threads.
// ---------------------------------------------------------------------------
template<int BM, int BN, int BK, int TM, int TN>
__global__ __launch_bounds__(256, 2)
void sgemm_bias_kernel(int M, int N, int K,
                       const float* __restrict__ A,
                       const float* __restrict__ Bm,
                       const float* __restrict__ bias,
                       float* __restrict__ Cm)
{
    __shared__ float As[BK][BM];   // A tile, K-major transposed for row-contig reads
    __shared__ float Bs[BK][BN];

    const int tid   = threadIdx.x;        // 256 threads: 16x16 microtile grid
    const int crow  = tid >> 4;           // 0..15  (M direction)
    const int ccol  = tid & 15;           // 0..15  (N direction)
    const int rowA0 = blockIdx.y * BM;
    const int colB0 = blockIdx.x * BN;

    // Global-load mapping (float4)
    const int aRow = tid >> 1;            // 0..127
    const int aCol = (tid & 1) * 4;       // 0 or 4 (BK=8)
    const int bRow = tid >> 5;            // 0..7
    const int bCol = (tid & 31) * 4;      // 0..124

    float acc[TM][TN];
#pragma unroll
    for (int i = 0; i < TM; i++)
#pragma unroll
        for (int j = 0; j < TN; j++) acc[i][j] = 0.f;

    const float* Ap = A  + (size_t)(rowA0 + aRow) * K + aCol;
    const float* Bp = Bm + (size_t)bRow * N + colB0 + bCol;

    for (int k0 = 0; k0 < K; k0 += BK) {
        float4 av = *(const float4*)(Ap + k0);
        As[aCol + 0][aRow] = av.x;
        As[aCol + 1][aRow] = av.y;
        As[aCol + 2][aRow] = av.z;
        As[aCol + 3][aRow] = av.w;
        *(float4*)&Bs[bRow][bCol] = *(const float4*)(Bp + (size_t)k0 * N);
        __syncthreads();

#pragma unroll
        for (int kk = 0; kk < BK; kk++) {
            float ar[TM], br[TN];
            *(float4*)&ar[0] = *(const float4*)&As[kk][crow * TM + 0];
            *(float4*)&ar[4] = *(const float4*)&As[kk][crow * TM + 4];
            *(float4*)&br[0] = *(const float4*)&Bs[kk][ccol * TN + 0];
            *(float4*)&br[4] = *(const float4*)&Bs[kk][ccol * TN + 4];
#pragma unroll
            for (int i = 0; i < TM; i++)
#pragma unroll
                for (int j = 0; j < TN; j++)
                    acc[i][j] = fmaf(ar[i], br[j], acc[i][j]);
        }
        __syncthreads();
    }

#pragma unroll
    for (int i = 0; i < TM; i++) {
        size_t r = (size_t)rowA0 + crow * TM + i;
#pragma unroll
        for (int j = 0; j < TN; j += 4) {
            int c = colB0 + ccol * TN + j;
            float4 o;
            o.x = acc[i][j + 0] + bias[c + 0];
            o.y = acc[i][j + 1] + bias[c + 1];
            o.z = acc[i][j + 2] + bias[c + 2];
            o.w = acc[i][j + 3] + bias[c + 3];
            *(float4*)(Cm + r * N + c) = o;
        }
    }
}

// ---------------------------------------------------------------------------
// Flash attention, fp32, causal. One block per (b, h, 64-row q tile).
// 256 threads as 16x16; each thread owns a 4x4 microtile of the 64x64 S / O.
// Smem: Qt[d][r], KP[ ][ ] (K transposed, reused as P natural), Vs[c][d].
// Exactly 48 KB static -> 2 blocks/SM.
// ---------------------------------------------------------------------------
__global__ __launch_bounds__(256, 2)
void flash_attn_kernel()
{
    __shared__ float Qt[Dh][64];   // Q^T, pre-scaled by 1/sqrt(Dh)
    __shared__ float KP[64][64];   // phase 1: K^T [d][c]; phase 2: P [r][c]
    __shared__ float Vs[64][64];   // V natural [c][d]

    const int tid = threadIdx.x;
    const int qt  = blockIdx.x;
    const int h   = blockIdx.y;
    const int b   = blockIdx.z;
    const int q0  = qt * 64;
    const int ty  = tid >> 4;      // row group 0..15
    const int tx  = tid & 15;      // col group 0..15

    const int tr  = tid >> 2;      // tile-load row 0..63
    const int tdg = tid & 3;       // tile-load d group

    const float scale = 0.125f;    // 1/sqrt(64)

    // Load Q transposed + pre-scaled
    {
        const float* qg = g_qkv + (size_t)(b * Ts + q0 + tr) * Nqkv + h * Dh;
#pragma unroll
        for (int l = 0; l < 4; l++) {
            int d = (tdg + l * 4) * 4;
            float4 v = *(const float4*)(qg + d);
            Qt[d + 0][tr] = v.x * scale;
            Qt[d + 1][tr] = v.y * scale;
            Qt[d + 2][tr] = v.z * scale;
            Qt[d + 3][tr] = v.w * scale;
        }
    }

    float m[4], l[4], o[4][4];
#pragma unroll
    for (int i = 0; i < 4; i++) {
        m[i] = -1e30f; l[i] = 0.f;
#pragma unroll
        for (int j = 0; j < 4; j++) o[i][j] = 0.f;
    }

    for (int kt = 0; kt <= qt; kt++) {
        const int k0 = kt * 64;
        __syncthreads();  // prev-iter PV readers done (also fences Qt on iter 0)

        // Load K^T and V tiles
        {
            const float* kg = g_qkv + (size_t)(b * Ts + k0 + tr) * Nqkv + Cc + h * Dh;
            const float* vg = kg + Cc;
#pragma unroll
            for (int ll = 0; ll < 4; ll++) {
                int d = (tdg + ll * 4) * 4;
                float4 kv = *(const float4*)(kg + d);
                KP[d + 0][tr] = kv.x;
                KP[d + 1][tr] = kv.y;
                KP[d + 2][tr] = kv.z;
                KP[d + 3][tr] = kv.w;
                *(float4*)&Vs[tr][d] = *(const float4*)(vg + d);
            }
        }
        __syncthreads();

        // S = (Q*scale) @ K^T   (64x64, 4x4 per thread)
        float s[4][4];
#pragma unroll
        for (int i = 0; i < 4; i++)
#pragma unroll
            for (int j = 0; j < 4; j++) s[i][j] = 0.f;

#pragma unroll 8
        for (int d = 0; d < Dh; d++) {
            float4 qv = *(const float4*)&Qt[d][ty * 4];
            float4 kv = *(const float4*)&KP[d][tx * 4];
            float qa[4] = {qv.x, qv.y, qv.z, qv.w};
            float ka[4] = {kv.x, kv.y, kv.z, kv.w};
#pragma unroll
            for (int i = 0; i < 4; i++)
#pragma unroll
                for (int j = 0; j < 4; j++)
                    s[i][j] = fmaf(qa[i], ka[j], s[i][j]);
        }

        // Causal mask on the diagonal tile (finite sentinel avoids inf-inf NaN)
        if (kt == qt) {
#pragma unroll
            for (int i = 0; i < 4; i++)
#pragma unroll
                for (int j = 0; j < 4; j++)
                    if (tx * 4 + j > ty * 4 + i) s[i][j] = -1e30f;
        }

        // Online softmax update (row reductions across the 16 tx lanes)
        float p[4][4];
#pragma unroll
        for (int i = 0; i < 4; i++) {
            float mx = fmaxf(fmaxf(s[i][0], s[i][1]), fmaxf(s[i][2], s[i][3]));
#pragma unroll
            for (int off = 8; off >= 1; off >>= 1)
                mx = fmaxf(mx, __shfl_xor_sync(0xffffffffu, mx, off));
            float mn = fmaxf(m[i], mx);
            float f  = __expf(m[i] - mn);
            m[i] = mn;
            float rs = 0.f;
#pragma unroll
            for (int j = 0; j < 4; j++) { p[i][j] = __expf(s[i][j] - mn); rs += p[i][j]; }
#pragma unroll
            for (int off = 8; off >= 1; off >>= 1)
                rs += __shfl_xor_sync(0xffffffffu, rs, off);
            l[i] = l[i] * f + rs;
#pragma unroll
            for (int j = 0; j < 4; j++) o[i][j] *= f;
        }

        __syncthreads();  // everyone done reading KP as K^T

        // Stash P into KP (natural layout [r][c])
#pragma unroll
        for (int i = 0; i < 4; i++)
            *(float4*)&KP[ty * 4 + i][tx * 4] =
                make_float4(p[i][0], p[i][1], p[i][2], p[i][3]);
        __syncthreads();

        // O += P @ V
#pragma unroll 8
        for (int c = 0; c < 64; c++) {
            float4 vv = *(const float4*)&Vs[c][tx * 4];
            float va[4] = {vv.x, vv.y, vv.z, vv.w};
            float pa[4];
#pragma unroll
            for (int i = 0; i < 4; i++) pa[i] = KP[ty * 4 + i][c];
#pragma unroll
            for (int i = 0; i < 4; i++)
#pragma unroll
                for (int j = 0; j < 4; j++)
                    o[i][j] = fmaf(pa[i], va[j], o[i][j]);
        }
    }

    // Epilogue: normalize and write attention output [b*T+t][h*Dh + d]
#pragma unroll
    for (int i = 0; i < 4; i++) {
        float inv = 1.0f / l[i];
        size_t r = (size_t)(b * Ts + q0 + ty * 4 + i) * Cc + h * Dh + tx * 4;
        *(float4*)(g_att + r) =
            make_float4(o[i][0] * inv, o[i][1] * inv, o[i][2] * inv, o[i][3] * inv);
    }
}

// ---------------------------------------------------------------------------
// Launch: QKV GEMM -> flash attention -> output GEMM. Graph-capturable.
// ---------------------------------------------------------------------------
extern "C" void kernel_launch(void* const* d_in, const int* in_sizes, int n_in,
                              void* d_out, int out_size)
{
    const float* x     = (const float*)d_in[0];
    const float* w_qkv = (const float*)d_in[1];
    const float* b_qkv = (const float*)d_in[2];
    const float* w_out = (const float*)d_in[3];
    const float* b_out = (const float*)d_in[4];
    float* out = (float*)d_out;

    float *qkv_ptr = nullptr, *att_ptr = nullptr;
    cudaGetSymbolAddress((void**)&qkv_ptr, g_qkv);
    cudaGetSymbolAddress((void**)&att_ptr, g_att);

    // 1) QKV projection: [8192,1024] @ [1024,3072] + bias
    {
        dim3 grid(Nqkv / 128, Mtot / 128);
        sgemm_bias_kernel<128, 128, 8, 8, 8><<<grid, 256>>>(
            Mtot, Nqkv, Cc, x, w_qkv, b_qkv, qkv_ptr);
    }

    // 2) Causal flash attention
    {
        dim3 grid(Ts / 64, Hh, Bb);
        flash_attn_kernel<<<grid, 256>>>();
    }

    // 3) Output projection: [8192,1024] @ [1024,1024] + bias
    {
        dim3 grid(Cc / 128, Mtot / 128);
        sgemm_bias_kernel<128, 128, 8, 8, 8><<<grid, 256>>>(
            Mtot, Cc, Cc, att_ptr, w_out, b_out, out);
    }
}

// round 8
// speedup vs baseline: 1.5120x; 1.5120x over previous
#include <cuda_runtime.h>
#include <cuda_fp16.h>
#include <cstdint>

// ---------------- problem constants ----------------
constexpr int Bb   = 4;
constexpr int Ts   = 2048;
constexpr int Cc   = 1024;
constexpr int Hh   = 16;
constexpr int Dh   = 64;
constexpr int Mtot = Bb * Ts;      // 8192
constexpr int Nqkv = 3 * Cc;       // 3072
constexpr int Kd   = Cc;           // 1024
constexpr int NCH  = Kd / 64;      // 16 k-chunks of 64

// ---------------- scratch (device globals) ----------------
__device__ float g_qkv[(size_t)Mtot * Nqkv];
__device__ float g_att[(size_t)Mtot * Cc];
__device__ __align__(1024) __half g_x_h[(size_t)Mtot * Kd];   // x hi  [M][K]
__device__ __align__(1024) __half g_x_l[(size_t)Mtot * Kd];   // x lo
__device__ __align__(1024) __half g_wq_h[(size_t)Nqkv * Kd];  // w_qkv^T hi [N][K]
__device__ __align__(1024) __half g_wq_l[(size_t)Nqkv * Kd];
__device__ __align__(1024) __half g_wo_h[(size_t)Cc * Kd];    // w_out^T hi [N][K]
__device__ __align__(1024) __half g_wo_l[(size_t)Cc * Kd];
__device__ __align__(1024) __half g_a_h[(size_t)Mtot * Kd];   // attn out hi [M][K]
__device__ __align__(1024) __half g_a_l[(size_t)Mtot * Kd];

// ---------------- PTX helpers (plain sm_80-level, compile for compute_103) ----
__device__ __forceinline__ uint32_t smem_u32(const void* p) {
    uint32_t a;
    asm("{ .reg .u64 t; cvta.to.shared.u64 t, %1; cvt.u32.u64 %0, t; }" : "=r"(a) : "l"(p));
    return a;
}
__device__ __forceinline__ void cpa16(uint32_t dst, const void* src) {
    asm volatile("cp.async.cg.shared.global [%0], [%1], 16;" :: "r"(dst), "l"(src));
}
__device__ __forceinline__ void cp_commit() {
    asm volatile("cp.async.commit_group;" ::: "memory");
}
template<int n>
__device__ __forceinline__ void cp_wait() {
    asm volatile("cp.async.wait_group %0;" :: "n"(n) : "memory");
}
__device__ __forceinline__ void ldsm4(uint32_t* r, uint32_t addr) {
    asm volatile("ldmatrix.sync.aligned.m8n8.x4.shared.b16 {%0,%1,%2,%3}, [%4];"
                 : "=r"(r[0]), "=r"(r[1]), "=r"(r[2]), "=r"(r[3]) : "r"(addr));
}
__device__ __forceinline__ void mma16816(float* d, const uint32_t* a, const uint32_t* b) {
    asm volatile(
        "mma.sync.aligned.m16n8k16.row.col.f32.f16.f16.f32 "
        "{%0,%1,%2,%3}, {%4,%5,%6,%7}, {%8,%9}, {%0,%1,%2,%3};"
        : "+f"(d[0]), "+f"(d[1]), "+f"(d[2]), "+f"(d[3])
        : "r"(a[0]), "r"(a[1]), "r"(a[2]), "r"(a[3]), "r"(b[0]), "r"(b[1]));
}

// ---------------------------------------------------------------------------
// conv_A: fp32 [rows,1024] row-major -> hi/lo fp16 row-major (one thread = 8 elems)
// lo = fp16(f - hi), unscaled (subnormal-ok; abs err <= 2^-24)
// ---------------------------------------------------------------------------
__global__ __launch_bounds__(256)
void conv_A(const float* __restrict__ src, __half* __restrict__ dh, __half* __restrict__ dl)
{
    size_t u = (size_t)blockIdx.x * 256 + threadIdx.x;   // 16B-unit index
    const float4* p = (const float4*)(src + u * 8);
    float4 f0 = p[0], f1 = p[1];
    float f[8] = {f0.x, f0.y, f0.z, f0.w, f1.x, f1.y, f1.z, f1.w};
    union { __half h[8]; uint4 v; } H, L;
#pragma unroll
    for (int j = 0; j < 8; j++) {
        __half hi = __float2half_rn(f[j]);
        H.h[j] = hi;
        L.h[j] = __float2half_rn(f[j] - __half2float(hi));
    }
    *(uint4*)(dh + u * 8) = H.v;
    *(uint4*)(dl + u * 8) = L.v;
}

// conv_B: fp32 weight [K=1024, N] row-major -> transposed [N][K] hi/lo
__global__ __launch_bounds__(256)
void conv_B(const float* __restrict__ w, __half* __restrict__ dh, __half* __restrict__ dl, int N)
{
    int n  = blockIdx.x * 256 + threadIdx.x;   // output row (N dim)
    int k0 = blockIdx.y * 8;                   // 8 consecutive k
    union { __half h[8]; uint4 v; } H, L;
#pragma unroll
    for (int j = 0; j < 8; j++) {
        float f = w[(size_t)(k0 + j) * N + n];
        __half hi = __float2half_rn(f);
        H.h[j] = hi;
        L.h[j] = __float2half_rn(f - __half2float(hi));
    }
    *(uint4*)(dh + (size_t)n * Kd + k0) = H.v;
    *(uint4*)(dl + (size_t)n * Kd + k0) = L.v;
}

// ---------------------------------------------------------------------------
// HMMA GEMM: C[M,N] = (Ah+Al) @ (Bh+Bl)^T + bias   (A:[M,K] hi/lo, B:[N,K] hi/lo)
// 128x128x64 block tile, 256 threads (2x4 warps, 64x32 warp tile),
// m16n8k16 f16*f16+f32, 2-stage cp.async double buffer, XOR-swizzled smem.
// Smem tile layout: [128 rows][64 halves], unit(16B) index u_phys = u ^ (row&7).
// ---------------------------------------------------------------------------
constexpr int TILE_HALVES = 128 * 64;             // one operand tile
constexpr int TILE_BYTES  = TILE_HALVES * 2;      // 16 KB
constexpr int STAGE_BYTES = 4 * TILE_BYTES;       // Ah, Al, Bh, Bl
constexpr int GEMM_SMEM   = 2 * STAGE_BYTES;      // 131072

__global__ __launch_bounds__(256, 1)
void gemm_hmma(const __half* __restrict__ Ah, const __half* __restrict__ Al,
               const __half* __restrict__ Bh, const __half* __restrict__ Bl,
               const float* __restrict__ bias, float* __restrict__ C, int N)
{
    extern __shared__ char smem_raw[];
    const uint32_t sbase = smem_u32(smem_raw);

    const int tid  = threadIdx.x;
    const int lane = tid & 31;
    const int wid  = tid >> 5;
    const int wm   = wid >> 2;          // 0..1  (M)
    const int wn   = wid & 3;           // 0..3  (N)
    const int bm   = blockIdx.y, bn = blockIdx.x;

    // cp.async mapping: thread t -> row r = t>>1, units u0..u0+3 (u0 = (t&1)*4)
    const int cr  = tid >> 1;
    const int cu0 = (tid & 1) * 4;
    const __half* srcs[4] = {
        Ah + (size_t)(bm * 128 + cr) * Kd,
        Al + (size_t)(bm * 128 + cr) * Kd,
        Bh + (size_t)(bn * 128 + cr) * Kd,
        Bl + (size_t)(bn * 128 + cr) * Kd
    };
    const uint32_t dstrow = (uint32_t)cr * 128;   // bytes within tile

    auto load_stage = [&](int s, int ch) {
        uint32_t sb = sbase + s * STAGE_BYTES;
#pragma unroll
        for (int t = 0; t < 4; t++) {
            const __half* src = srcs[t] + ch * 64;
            uint32_t tb = sb + t * TILE_BYTES + dstrow;
#pragma unroll
            for (int j = 0; j < 4; j++) {
                int u = cu0 + j;
                cpa16(tb + ((u ^ (cr & 7)) * 16), src + u * 8);
            }
        }
    };

    float acc[4][4][4];
#pragma unroll
    for (int i = 0; i < 4; i++)
#pragma unroll
        for (int j = 0; j < 4; j++)
#pragma unroll
            for (int k = 0; k < 4; k++) acc[i][j][k] = 0.f;

    // per-thread ldmatrix row bases (row = lane&15, k-group = lane>>4)
    const int rA = lane & 15, kg = lane >> 4;
    uint32_t arow[4], brow[4];
    int as7[4], bs7[4];
#pragma unroll
    for (int mi = 0; mi < 4; mi++) {
        int r = wm * 64 + mi * 16 + rA;
        arow[mi] = (uint32_t)r * 128; as7[mi] = r & 7;
    }
#pragma unroll
    for (int np = 0; np < 2; np++) {
        int r = wn * 32 + np * 16 + rA;
        brow[np] = (uint32_t)r * 128; bs7[np] = r & 7;
    }

    load_stage(0, 0);
    cp_commit();

    for (int i = 0; i < NCH; i++) {
        if (i + 1 < NCH) { load_stage((i + 1) & 1, i + 1); cp_commit(); cp_wait<1>(); }
        else             { cp_wait<0>(); }
        __syncthreads();

        uint32_t sb = sbase + (i & 1) * STAGE_BYTES;
#pragma unroll
        for (int ks = 0; ks < 4; ks++) {
            uint32_t ah[4][4], al[4][4], bh[4][2], bl[4][2];
            int kb = ks * 2 + kg;
#pragma unroll
            for (int mi = 0; mi < 4; mi++) {
                uint32_t off = arow[mi] + (uint32_t)((kb ^ as7[mi]) * 16);
                ldsm4(ah[mi], sb + off);
                ldsm4(al[mi], sb + TILE_BYTES + off);
            }
#pragma unroll
            for (int np = 0; np < 2; np++) {
                uint32_t off = brow[np] + (uint32_t)((kb ^ bs7[np]) * 16);
                uint32_t t[4];
                ldsm4(t, sb + 2 * TILE_BYTES + off);
                bh[2*np][0] = t[0]; bh[2*np+1][0] = t[1];
                bh[2*np][1] = t[2]; bh[2*np+1][1] = t[3];
                ldsm4(t, sb + 3 * TILE_BYTES + off);
                bl[2*np][0] = t[0]; bl[2*np+1][0] = t[1];
                bl[2*np][1] = t[2]; bl[2*np+1][1] = t[3];
            }
#pragma unroll
            for (int mi = 0; mi < 4; mi++)
#pragma unroll
                for (int ni = 0; ni < 4; ni++) {
                    mma16816(acc[mi][ni], ah[mi], bh[ni]);   // hi*hi
                    mma16816(acc[mi][ni], ah[mi], bl[ni]);   // hi*lo
                    mma16816(acc[mi][ni], al[mi], bh[ni]);   // lo*hi
                }
        }
        __syncthreads();
    }

    // epilogue: c-frag lane mapping (m = lane/4 [+8], n = (lane%4)*2 +{0,1})
    const int er = lane >> 2, ec = (lane & 3) * 2;
#pragma unroll
    for (int mi = 0; mi < 4; mi++) {
        size_t r0 = (size_t)bm * 128 + wm * 64 + mi * 16 + er;
#pragma unroll
        for (int ni = 0; ni < 4; ni++) {
            int c = bn * 128 + wn * 32 + ni * 8 + ec;
            float2 bv = *(const float2*)(bias + c);
            float2 o0 = { acc[mi][ni][0] + bv.x, acc[mi][ni][1] + bv.y };
            float2 o1 = { acc[mi][ni][2] + bv.x, acc[mi][ni][3] + bv.y };
            *(float2*)(C + r0 * N + c)       = o0;
            *(float2*)(C + (r0 + 8) * N + c) = o1;
        }
    }
}

// ---------------------------------------------------------------------------
// Flash attention, fp32, causal (unchanged known-good from round 4).
// ---------------------------------------------------------------------------
__global__ __launch_bounds__(256, 2)
void flash_attn_kernel()
{
    __shared__ float Qt[Dh][64];
    __shared__ float KP[64][64];
    __shared__ float Vs[64][64];

    const int tid = threadIdx.x;
    const int qt  = blockIdx.x;
    const int h   = blockIdx.y;
    const int b   = blockIdx.z;
    const int q0  = qt * 64;
    const int ty  = tid >> 4;
    const int tx  = tid & 15;
    const int tr  = tid >> 2;
    const int tdg = tid & 3;
    const float scale = 0.125f;

    {
        const float* qg = g_qkv + (size_t)(b * Ts + q0 + tr) * Nqkv + h * Dh;
#pragma unroll
        for (int l = 0; l < 4; l++) {
            int d = (tdg + l * 4) * 4;
            float4 v = *(const float4*)(qg + d);
            Qt[d + 0][tr] = v.x * scale;
            Qt[d + 1][tr] = v.y * scale;
            Qt[d + 2][tr] = v.z * scale;
            Qt[d + 3][tr] = v.w * scale;
        }
    }

    float m[4], l[4], o[4][4];
#pragma unroll
    for (int i = 0; i < 4; i++) {
        m[i] = -1e30f; l[i] = 0.f;
#pragma unroll
        for (int j = 0; j < 4; j++) o[i][j] = 0.f;
    }

    for (int kt = 0; kt <= qt; kt++) {
        const int k0 = kt * 64;
        __syncthreads();
        {
            const float* kg = g_qkv + (size_t)(b * Ts + k0 + tr) * Nqkv + Cc + h * Dh;
            const float* vg = kg + Cc;
#pragma unroll
            for (int ll = 0; ll < 4; ll++) {
                int d = (tdg + ll * 4) * 4;
                float4 kv = *(const float4*)(kg + d);
                KP[d + 0][tr] = kv.x;
                KP[d + 1][tr] = kv.y;
                KP[d + 2][tr] = kv.z;
                KP[d + 3][tr] = kv.w;
                *(float4*)&Vs[tr][d] = *(const float4*)(vg + d);
            }
        }
        __syncthreads();

        float s[4][4];
#pragma unroll
        for (int i = 0; i < 4; i++)
#pragma unroll
            for (int j = 0; j < 4; j++) s[i][j] = 0.f;

#pragma unroll 8
        for (int d = 0; d < Dh; d++) {
            float4 qv = *(const float4*)&Qt[d][ty * 4];
            float4 kv = *(const float4*)&KP[d][tx * 4];
            float qa[4] = {qv.x, qv.y, qv.z, qv.w};
            float ka[4] = {kv.x, kv.y, kv.z, kv.w};
#pragma unroll
            for (int i = 0; i < 4; i++)
#pragma unroll
                for (int j = 0; j < 4; j++)
                    s[i][j] = fmaf(qa[i], ka[j], s[i][j]);
        }

        if (kt == qt) {
#pragma unroll
            for (int i = 0; i < 4; i++)
#pragma unroll
                for (int j = 0; j < 4; j++)
                    if (tx * 4 + j > ty * 4 + i) s[i][j] = -1e30f;
        }

        float p[4][4];
#pragma unroll
        for (int i = 0; i < 4; i++) {
            float mx = fmaxf(fmaxf(s[i][0], s[i][1]), fmaxf(s[i][2], s[i][3]));
#pragma unroll
            for (int off = 8; off >= 1; off >>= 1)
                mx = fmaxf(mx, __shfl_xor_sync(0xffffffffu, mx, off));
            float mn = fmaxf(m[i], mx);
            float f  = __expf(m[i] - mn);
            m[i] = mn;
            float rs = 0.f;
#pragma unroll
            for (int j = 0; j < 4; j++) { p[i][j] = __expf(s[i][j] - mn); rs += p[i][j]; }
#pragma unroll
            for (int off = 8; off >= 1; off >>= 1)
                rs += __shfl_xor_sync(0xffffffffu, rs, off);
            l[i] = l[i] * f + rs;
#pragma unroll
            for (int j = 0; j < 4; j++) o[i][j] *= f;
        }

        __syncthreads();
#pragma unroll
        for (int i = 0; i < 4; i++)
            *(float4*)&KP[ty * 4 + i][tx * 4] =
                make_float4(p[i][0], p[i][1], p[i][2], p[i][3]);
        __syncthreads();

#pragma unroll 8
        for (int c = 0; c < 64; c++) {
            float4 vv = *(const float4*)&Vs[c][tx * 4];
            float va[4] = {vv.x, vv.y, vv.z, vv.w};
            float pa[4];
#pragma unroll
            for (int i = 0; i < 4; i++) pa[i] = KP[ty * 4 + i][c];
#pragma unroll
            for (int i = 0; i < 4; i++)
#pragma unroll
                for (int j = 0; j < 4; j++)
                    o[i][j] = fmaf(pa[i], va[j], o[i][j]);
        }
    }

#pragma unroll
    for (int i = 0; i < 4; i++) {
        float inv = 1.0f / l[i];
        size_t r = (size_t)(b * Ts + q0 + ty * 4 + i) * Cc + h * Dh + tx * 4;
        *(float4*)(g_att + r) =
            make_float4(o[i][0] * inv, o[i][1] * inv, o[i][2] * inv, o[i][3] * inv);
    }
}

// ---------------------------------------------------------------------------
// Launch (graph-capturable: kernels only)
// ---------------------------------------------------------------------------
extern "C" void kernel_launch(void* const* d_in, const int* in_sizes, int n_in,
                              void* d_out, int out_size)
{
    const float* x     = (const float*)d_in[0];
    const float* w_qkv = (const float*)d_in[1];
    const float* b_qkv = (const float*)d_in[2];
    const float* w_out = (const float*)d_in[3];
    const float* b_out = (const float*)d_in[4];
    float* out = (float*)d_out;

    float *qkv_ptr, *att_ptr;
    __half *xh, *xl, *wqh, *wql, *woh, *wol, *ah, *al;
    cudaGetSymbolAddress((void**)&qkv_ptr, g_qkv);
    cudaGetSymbolAddress((void**)&att_ptr, g_att);
    cudaGetSymbolAddress((void**)&xh,  g_x_h);  cudaGetSymbolAddress((void**)&xl,  g_x_l);
    cudaGetSymbolAddress((void**)&wqh, g_wq_h); cudaGetSymbolAddress((void**)&wql, g_wq_l);
    cudaGetSymbolAddress((void**)&woh, g_wo_h); cudaGetSymbolAddress((void**)&wol, g_wo_l);
    cudaGetSymbolAddress((void**)&ah,  g_a_h);  cudaGetSymbolAddress((void**)&al,  g_a_l);

    cudaFuncSetAttribute(gemm_hmma, cudaFuncAttributeMaxDynamicSharedMemorySize, GEMM_SMEM);

    // 0) operand conversion
    conv_A<<<(int)(((size_t)Mtot * Kd / 8) / 256), 256>>>(x, xh, xl);
    conv_B<<<dim3(Nqkv / 256, Kd / 8), 256>>>(w_qkv, wqh, wql, Nqkv);
    conv_B<<<dim3(Cc / 256, Kd / 8), 256>>>(w_out, woh, wol, Cc);

    // 1) QKV projection (HMMA): [8192,1024] @ [1024,3072] + bias
    gemm_hmma<<<dim3(Nqkv / 128, Mtot / 128), 256, GEMM_SMEM>>>(
        xh, xl, wqh, wql, b_qkv, qkv_ptr, Nqkv);

    // 2) causal flash attention (fp32)
    flash_attn_kernel<<<dim3(Ts / 64, Hh, Bb), 256>>>();

    // 3) attention output -> hi/lo, then output projection (HMMA)
    conv_A<<<(int)(((size_t)Mtot * Kd / 8) / 256), 256>>>(att_ptr, ah, al);
    gemm_hmma<<<dim3(Cc / 128, Mtot / 128), 256, GEMM_SMEM>>>(
        ah, al, woh, wol, b_out, out, Cc);
}

// round 9
// speedup vs baseline: 2.3498x; 1.5542x over previous
#include <cuda_runtime.h>
#include <cuda_fp16.h>
#include <cstdint>

// ---------------- problem constants ----------------
constexpr int Bb   = 4;
constexpr int Ts   = 2048;
constexpr int Cc   = 1024;
constexpr int Hh   = 16;
constexpr int Dh   = 64;
constexpr int Mtot = Bb * Ts;      // 8192
constexpr int Nqkv = 3 * Cc;       // 3072
constexpr int Kd   = Cc;           // 1024
constexpr int NCH  = Kd / 64;      // 16 k-chunks of 64

// ---------------- scratch (device globals) ----------------
__device__ float g_qkv[(size_t)Mtot * Nqkv];
__device__ __align__(1024) __half g_x_h[(size_t)Mtot * Kd];   // x hi  [M][K]
__device__ __align__(1024) __half g_x_l[(size_t)Mtot * Kd];
__device__ __align__(1024) __half g_wq_h[(size_t)Nqkv * Kd];  // w_qkv^T hi [N][K]
__device__ __align__(1024) __half g_wq_l[(size_t)Nqkv * Kd];
__device__ __align__(1024) __half g_wo_h[(size_t)Cc * Kd];    // w_out^T hi [N][K]
__device__ __align__(1024) __half g_wo_l[(size_t)Cc * Kd];
__device__ __align__(1024) __half g_a_h[(size_t)Mtot * Kd];   // attn out hi [M][K]
__device__ __align__(1024) __half g_a_l[(size_t)Mtot * Kd];
// attention operands, per-head layouts
__device__ __align__(1024) __half g_q_h[(size_t)Bb * Hh * Ts * Dh];   // [b,h,t,d] (pre-scaled)
__device__ __align__(1024) __half g_q_l[(size_t)Bb * Hh * Ts * Dh];
__device__ __align__(1024) __half g_k_h[(size_t)Bb * Hh * Ts * Dh];   // [b,h,t,d]
__device__ __align__(1024) __half g_k_l[(size_t)Bb * Hh * Ts * Dh];
__device__ __align__(1024) __half g_vt_h[(size_t)Bb * Hh * Dh * Ts];  // [b,h,d,t]
__device__ __align__(1024) __half g_vt_l[(size_t)Bb * Hh * Dh * Ts];

// ---------------- PTX helpers (sm_80-level, compile for compute_103) --------
__device__ __forceinline__ uint32_t smem_u32(const void* p) {
    uint32_t a;
    asm("{ .reg .u64 t; cvta.to.shared.u64 t, %1; cvt.u32.u64 %0, t; }" : "=r"(a) : "l"(p));
    return a;
}
__device__ __forceinline__ void cpa16(uint32_t dst, const void* src) {
    asm volatile("cp.async.cg.shared.global [%0], [%1], 16;" :: "r"(dst), "l"(src));
}
__device__ __forceinline__ void cp_commit() {
    asm volatile("cp.async.commit_group;" ::: "memory");
}
template<int n>
__device__ __forceinline__ void cp_wait() {
    asm volatile("cp.async.wait_group %0;" :: "n"(n) : "memory");
}
__device__ __forceinline__ void ldsm4(uint32_t* r, uint32_t addr) {
    asm volatile("ldmatrix.sync.aligned.m8n8.x4.shared.b16 {%0,%1,%2,%3}, [%4];"
                 : "=r"(r[0]), "=r"(r[1]), "=r"(r[2]), "=r"(r[3]) : "r"(addr));
}
__device__ __forceinline__ void mma16816(float* d, const uint32_t* a, const uint32_t* b) {
    asm volatile(
        "mma.sync.aligned.m16n8k16.row.col.f32.f16.f16.f32 "
        "{%0,%1,%2,%3}, {%4,%5,%6,%7}, {%8,%9}, {%0,%1,%2,%3};"
        : "+f"(d[0]), "+f"(d[1]), "+f"(d[2]), "+f"(d[3])
        : "r"(a[0]), "r"(a[1]), "r"(a[2]), "r"(a[3]), "r"(b[0]), "r"(b[1]));
}
// split (x,y) into hi half2 + lo half2 (residual)
__device__ __forceinline__ void pack_hilo(float x, float y, uint32_t& h, uint32_t& l) {
    __half2 hh = __floats2half2_rn(x, y);
    float2 hf = __half22float2(hh);
    __half2 ll = __floats2half2_rn(x - hf.x, y - hf.y);
    h = *(uint32_t*)&hh;
    l = *(uint32_t*)&ll;
}

// ---------------------------------------------------------------------------
// conv_A: fp32 [rows,1024] -> hi/lo fp16 row-major (8 elems/thread)
// ---------------------------------------------------------------------------
__global__ __launch_bounds__(256)
void conv_A(const float* __restrict__ src, __half* __restrict__ dh, __half* __restrict__ dl)
{
    size_t u = (size_t)blockIdx.x * 256 + threadIdx.x;
    const float4* p = (const float4*)(src + u * 8);
    float4 f0 = p[0], f1 = p[1];
    float f[8] = {f0.x, f0.y, f0.z, f0.w, f1.x, f1.y, f1.z, f1.w};
    union { __half h[8]; uint4 v; } H, L;
#pragma unroll
    for (int j = 0; j < 8; j++) {
        __half hi = __float2half_rn(f[j]);
        H.h[j] = hi;
        L.h[j] = __float2half_rn(f[j] - __half2float(hi));
    }
    *(uint4*)(dh + u * 8) = H.v;
    *(uint4*)(dl + u * 8) = L.v;
}

// conv_B: fp32 weight [K,N] -> transposed [N][K] hi/lo
__global__ __launch_bounds__(256)
void conv_B(const float* __restrict__ w, __half* __restrict__ dh, __half* __restrict__ dl, int N)
{
    int n  = blockIdx.x * 256 + threadIdx.x;
    int k0 = blockIdx.y * 8;
    union { __half h[8]; uint4 v; } H, L;
#pragma unroll
    for (int j = 0; j < 8; j++) {
        float f = w[(size_t)(k0 + j) * N + n];
        __half hi = __float2half_rn(f);
        H.h[j] = hi;
        L.h[j] = __float2half_rn(f - __half2float(hi));
    }
    *(uint4*)(dh + (size_t)n * Kd + k0) = H.v;
    *(uint4*)(dl + (size_t)n * Kd + k0) = L.v;
}

// ---------------------------------------------------------------------------
// conv_qkv: g_qkv fp32 -> Q(hi/lo, pre-scaled) [b,h,t,d], K(hi/lo) [b,h,t,d],
//           V^T(hi/lo) [b,h,d,t].  grid (Ts/64, Hh, Bb), 256 thr.
// ---------------------------------------------------------------------------
__global__ __launch_bounds__(256)
void conv_qkv()
{
    __shared__ float vs[64][65];
    const int b = blockIdx.z, h = blockIdx.y, t0 = blockIdx.x * 64;
    const int tid = threadIdx.x;
    const int tl = tid >> 2;             // token-local 0..63
    const int d0 = (tid & 3) * 16;       // 16 d per thread
    const float* src = g_qkv + ((size_t)b * Ts + t0 + tl) * Nqkv + h * Dh + d0;
    const size_t qk_off = ((size_t)(b * Hh + h) * Ts + t0 + tl) * Dh + d0;

    union { __half hh[16]; uint4 v[2]; } QH_, QL_, KH_, KL_;
#pragma unroll
    for (int j = 0; j < 16; j++) {
        float q = src[j] * 0.125f;                 // fold 1/sqrt(Dh)
        __half qh = __float2half_rn(q);
        QH_.hh[j] = qh;
        QL_.hh[j] = __float2half_rn(q - __half2float(qh));
        float k = src[Cc + j];
        __half kh = __float2half_rn(k);
        KH_.hh[j] = kh;
        KL_.hh[j] = __float2half_rn(k - __half2float(kh));
        vs[tl][d0 + j] = src[2 * Cc + j];          // V row into smem
    }
    *(uint4*)(g_q_h + qk_off) = QH_.v[0]; *(uint4*)(g_q_h + qk_off + 8) = QH_.v[1];
    *(uint4*)(g_q_l + qk_off) = QL_.v[0]; *(uint4*)(g_q_l + qk_off + 8) = QL_.v[1];
    *(uint4*)(g_k_h + qk_off) = KH_.v[0]; *(uint4*)(g_k_h + qk_off + 8) = KH_.v[1];
    *(uint4*)(g_k_l + qk_off) = KL_.v[0]; *(uint4*)(g_k_l + qk_off + 8) = KL_.v[1];
    __syncthreads();

    // V transpose: thread -> d = tid>>2, 16 t-cols
    const int d  = tid >> 2;
    const int tg = (tid & 3) * 16;
    union { __half hh[16]; uint4 v[2]; } VH_, VL_;
#pragma unroll
    for (int j = 0; j < 16; j++) {
        float f = vs[tg + j][d];
        __half hi = __float2half_rn(f);
        VH_.hh[j] = hi;
        VL_.hh[j] = __float2half_rn(f - __half2float(hi));
    }
    size_t vt_off = ((size_t)(b * Hh + h) * Dh + d) * Ts + t0 + tg;
    *(uint4*)(g_vt_h + vt_off) = VH_.v[0]; *(uint4*)(g_vt_h + vt_off + 8) = VH_.v[1];
    *(uint4*)(g_vt_l + vt_off) = VL_.v[0]; *(uint4*)(g_vt_l + vt_off + 8) = VL_.v[1];
}

// ---------------------------------------------------------------------------
// HMMA GEMM (unchanged, known-good from round 8)
// ---------------------------------------------------------------------------
constexpr int TILE_HALVES = 128 * 64;
constexpr int TILE_BYTES  = TILE_HALVES * 2;      // 16 KB
constexpr int STAGE_BYTES = 4 * TILE_BYTES;       // Ah, Al, Bh, Bl
constexpr int GEMM_SMEM   = 2 * STAGE_BYTES;      // 131072

__global__ __launch_bounds__(256, 1)
void gemm_hmma(const __half* __restrict__ Ah, const __half* __restrict__ Al,
               const __half* __restrict__ Bh, const __half* __restrict__ Bl,
               const float* __restrict__ bias, float* __restrict__ C, int N)
{
    extern __shared__ char smem_raw[];
    const uint32_t sbase = smem_u32(smem_raw);

    const int tid  = threadIdx.x;
    const int lane = tid & 31;
    const int wid  = tid >> 5;
    const int wm   = wid >> 2;
    const int wn   = wid & 3;
    const int bm   = blockIdx.y, bn = blockIdx.x;

    const int cr  = tid >> 1;
    const int cu0 = (tid & 1) * 4;
    const __half* srcs[4] = {
        Ah + (size_t)(bm * 128 + cr) * Kd,
        Al + (size_t)(bm * 128 + cr) * Kd,
        Bh + (size_t)(bn * 128 + cr) * Kd,
        Bl + (size_t)(bn * 128 + cr) * Kd
    };
    const uint32_t dstrow = (uint32_t)cr * 128;

    auto load_stage = [&](int s, int ch) {
        uint32_t sb = sbase + s * STAGE_BYTES;
#pragma unroll
        for (int t = 0; t < 4; t++) {
            const __half* src = srcs[t] + ch * 64;
            uint32_t tb = sb + t * TILE_BYTES + dstrow;
#pragma unroll
            for (int j = 0; j < 4; j++) {
                int u = cu0 + j;
                cpa16(tb + ((u ^ (cr & 7)) * 16), src + u * 8);
            }
        }
    };

    float acc[4][4][4];
#pragma unroll
    for (int i = 0; i < 4; i++)
#pragma unroll
        for (int j = 0; j < 4; j++)
#pragma unroll
            for (int k = 0; k < 4; k++) acc[i][j][k] = 0.f;

    const int rA = lane & 15, kg = lane >> 4;
    uint32_t arow[4], brow[4];
    int as7[4], bs7[4];
#pragma unroll
    for (int mi = 0; mi < 4; mi++) {
        int r = wm * 64 + mi * 16 + rA;
        arow[mi] = (uint32_t)r * 128; as7[mi] = r & 7;
    }
#pragma unroll
    for (int np = 0; np < 2; np++) {
        int r = wn * 32 + np * 16 + rA;
        brow[np] = (uint32_t)r * 128; bs7[np] = r & 7;
    }

    load_stage(0, 0);
    cp_commit();

    for (int i = 0; i < NCH; i++) {
        if (i + 1 < NCH) { load_stage((i + 1) & 1, i + 1); cp_commit(); cp_wait<1>(); }
        else             { cp_wait<0>(); }
        __syncthreads();

        uint32_t sb = sbase + (i & 1) * STAGE_BYTES;
#pragma unroll
        for (int ks = 0; ks < 4; ks++) {
            uint32_t ah[4][4], al[4][4], bh[4][2], bl[4][2];
            int kb = ks * 2 + kg;
#pragma unroll
            for (int mi = 0; mi < 4; mi++) {
                uint32_t off = arow[mi] + (uint32_t)((kb ^ as7[mi]) * 16);
                ldsm4(ah[mi], sb + off);
                ldsm4(al[mi], sb + TILE_BYTES + off);
            }
#pragma unroll
            for (int np = 0; np < 2; np++) {
                uint32_t off = brow[np] + (uint32_t)((kb ^ bs7[np]) * 16);
                uint32_t t[4];
                ldsm4(t, sb + 2 * TILE_BYTES + off);
                bh[2*np][0] = t[0]; bh[2*np+1][0] = t[1];
                bh[2*np][1] = t[2]; bh[2*np+1][1] = t[3];
                ldsm4(t, sb + 3 * TILE_BYTES + off);
                bl[2*np][0] = t[0]; bl[2*np+1][0] = t[1];
                bl[2*np][1] = t[2]; bl[2*np+1][1] = t[3];
            }
#pragma unroll
            for (int mi = 0; mi < 4; mi++)
#pragma unroll
                for (int ni = 0; ni < 4; ni++) {
                    mma16816(acc[mi][ni], ah[mi], bh[ni]);
                    mma16816(acc[mi][ni], ah[mi], bl[ni]);
                    mma16816(acc[mi][ni], al[mi], bh[ni]);
                }
        }
        __syncthreads();
    }

    const int er = lane >> 2, ec = (lane & 3) * 2;
#pragma unroll
    for (int mi = 0; mi < 4; mi++) {
        size_t r0 = (size_t)bm * 128 + wm * 64 + mi * 16 + er;
#pragma unroll
        for (int ni = 0; ni < 4; ni++) {
            int c = bn * 128 + wn * 32 + ni * 8 + ec;
            float2 bv = *(const float2*)(bias + c);
            float2 o0 = { acc[mi][ni][0] + bv.x, acc[mi][ni][1] + bv.y };
            float2 o1 = { acc[mi][ni][2] + bv.x, acc[mi][ni][3] + bv.y };
            *(float2*)(C + r0 * N + c)       = o0;
            *(float2*)(C + (r0 + 8) * N + c) = o1;
        }
    }
}

// ---------------------------------------------------------------------------
// flash_hmma: causal flash attention on mma.sync, hi/lo fp16 everywhere.
// Block = 128 q-rows (8 warps x 16), KV tile = 64, double-buffered cp.async.
// Writes O/l directly as hi/lo halves into the out-projection A operand.
// ---------------------------------------------------------------------------
constexpr int ATT_SMEM = 32768 /*Q hi+lo*/ + 2 * 32768 /*KV stages*/;  // 98304

__global__ __launch_bounds__(256, 1)
void flash_hmma()
{
    extern __shared__ char sm[];
    const uint32_t sb  = smem_u32(sm);
    const uint32_t QHs = sb, QLs = sb + 16384;

    const int tid = threadIdx.x, lane = tid & 31, wq = tid >> 5;
    const int qt = blockIdx.x, h = blockIdx.y, b = blockIdx.z;
    const int q0 = qt * 128;
    const int ktmax = 2 * qt + 1;

    const size_t bh = (size_t)(b * Hh + h);
    const __half* Qh = g_q_h + (bh * Ts + q0) * Dh;
    const __half* Ql = g_q_l + (bh * Ts + q0) * Dh;
    const __half* Kh = g_k_h + bh * Ts * Dh;
    const __half* Kl = g_k_l + bh * Ts * Dh;
    const __half* Vh = g_vt_h + bh * Dh * Ts;
    const __half* Vl = g_vt_l + bh * Dh * Ts;

    // Q tile loads (128 rows x 8 units, hi+lo)
    {
        int qr = tid >> 1, u0 = (tid & 1) * 4;
#pragma unroll
        for (int j = 0; j < 4; j++) {
            int u = u0 + j; int ph = u ^ (qr & 7);
            cpa16(QHs + qr * 128 + ph * 16, Qh + (size_t)qr * 64 + u * 8);
            cpa16(QLs + qr * 128 + ph * 16, Ql + (size_t)qr * 64 + u * 8);
        }
    }
    // KV stage loads: 64 rows x 8 units x 4 arrays (Kh,Kl,VTh,VTl)
    const int kr = tid >> 2, ku0 = (tid & 3) * 2;
    auto load_kv = [&](int s, int kt) {
        uint32_t base = sb + 32768 + s * 32768;
        int k0 = kt * 64;
#pragma unroll
        for (int j = 0; j < 2; j++) {
            int u = ku0 + j; int ph = u ^ (kr & 7);
            uint32_t o = kr * 128 + ph * 16;
            cpa16(base + o,         Kh + (size_t)(k0 + kr) * 64 + u * 8);
            cpa16(base + 8192 + o,  Kl + (size_t)(k0 + kr) * 64 + u * 8);
            cpa16(base + 16384 + o, Vh + (size_t)kr * Ts + k0 + u * 8);
            cpa16(base + 24576 + o, Vl + (size_t)kr * Ts + k0 + u * 8);
        }
    };
    load_kv(0, 0);
    cp_commit();
    load_kv(1, 1);          // ktmax >= 1 always
    cp_commit();
    cp_wait<1>();
    __syncthreads();

    // Q fragments (A operand), resident for the whole block
    uint32_t qfh[4][4], qfl[4][4];
    {
        int row = wq * 16 + (lane & 15);
#pragma unroll
        for (int ks = 0; ks < 4; ks++) {
            int u = ks * 2 + (lane >> 4); int ph = u ^ (row & 7);
            uint32_t o = row * 128 + ph * 16;
            ldsm4(qfh[ks], QHs + o);
            ldsm4(qfl[ks], QLs + o);
        }
    }

    float m0 = -1e30f, m1 = -1e30f, l0 = 0.f, l1 = 0.f;
    float oacc[8][4];
#pragma unroll
    for (int i = 0; i < 8; i++)
#pragma unroll
        for (int j = 0; j < 4; j++) oacc[i][j] = 0.f;

    const int rg0 = q0 + wq * 16 + (lane >> 2);   // global row of c-frag row 0

    for (int kt = 0; kt <= ktmax; kt++) {
        if (kt > 0) {
            if (kt + 1 <= ktmax) { load_kv((kt + 1) & 1, kt + 1); cp_commit(); cp_wait<1>(); }
            else                 { cp_wait<0>(); }
            __syncthreads();
        }
        const uint32_t kb = sb + 32768 + (kt & 1) * 32768;
        const int k0 = kt * 64;

        if (k0 <= q0 + wq * 16 + 15) {   // warp not fully above diagonal
            // ---- S = Q @ K^T (3 hi/lo passes)
            float sacc[8][4];
#pragma unroll
            for (int i = 0; i < 8; i++)
#pragma unroll
                for (int j = 0; j < 4; j++) sacc[i][j] = 0.f;

#pragma unroll
            for (int ks = 0; ks < 4; ks++) {
#pragma unroll
                for (int np = 0; np < 4; np++) {
                    int row = np * 16 + (lane & 15);
                    int u = ks * 2 + (lane >> 4); int ph = u ^ (row & 7);
                    uint32_t o = row * 128 + ph * 16;
                    uint32_t th[4], tl[4];
                    ldsm4(th, kb + o);
                    ldsm4(tl, kb + 8192 + o);
                    uint32_t beh[2] = {th[0], th[2]}, boh[2] = {th[1], th[3]};
                    uint32_t bel[2] = {tl[0], tl[2]}, bol[2] = {tl[1], tl[3]};
                    mma16816(sacc[2*np],   qfh[ks], beh);
                    mma16816(sacc[2*np],   qfh[ks], bel);
                    mma16816(sacc[2*np],   qfl[ks], beh);
                    mma16816(sacc[2*np+1], qfh[ks], boh);
                    mma16816(sacc[2*np+1], qfh[ks], bol);
                    mma16816(sacc[2*np+1], qfl[ks], boh);
                }
            }
            // ---- causal mask (diagonal region only)
            if (k0 + 63 > q0 + wq * 16) {
#pragma unroll
                for (int nt = 0; nt < 8; nt++) {
                    int cg = k0 + nt * 8 + (lane & 3) * 2;
                    if (cg     > rg0)     sacc[nt][0] = -1e30f;
                    if (cg + 1 > rg0)     sacc[nt][1] = -1e30f;
                    if (cg     > rg0 + 8) sacc[nt][2] = -1e30f;
                    if (cg + 1 > rg0 + 8) sacc[nt][3] = -1e30f;
                }
            }
            // ---- online softmax (rows r, r+8 per lane)
            float mx0 = -1e30f, mx1 = -1e30f;
#pragma unroll
            for (int nt = 0; nt < 8; nt++) {
                mx0 = fmaxf(mx0, fmaxf(sacc[nt][0], sacc[nt][1]));
                mx1 = fmaxf(mx1, fmaxf(sacc[nt][2], sacc[nt][3]));
            }
            mx0 = fmaxf(mx0, __shfl_xor_sync(0xffffffffu, mx0, 1));
            mx0 = fmaxf(mx0, __shfl_xor_sync(0xffffffffu, mx0, 2));
            mx1 = fmaxf(mx1, __shfl_xor_sync(0xffffffffu, mx1, 1));
            mx1 = fmaxf(mx1, __shfl_xor_sync(0xffffffffu, mx1, 2));
            float mn0 = fmaxf(m0, mx0), mn1 = fmaxf(m1, mx1);
            float f0 = __expf(m0 - mn0), f1 = __expf(m1 - mn1);
            m0 = mn0; m1 = mn1;
            float rs0 = 0.f, rs1 = 0.f;
#pragma unroll
            for (int nt = 0; nt < 8; nt++) {
                sacc[nt][0] = __expf(sacc[nt][0] - mn0); rs0 += sacc[nt][0];
                sacc[nt][1] = __expf(sacc[nt][1] - mn0); rs0 += sacc[nt][1];
                sacc[nt][2] = __expf(sacc[nt][2] - mn1); rs1 += sacc[nt][2];
                sacc[nt][3] = __expf(sacc[nt][3] - mn1); rs1 += sacc[nt][3];
            }
            rs0 += __shfl_xor_sync(0xffffffffu, rs0, 1);
            rs0 += __shfl_xor_sync(0xffffffffu, rs0, 2);
            rs1 += __shfl_xor_sync(0xffffffffu, rs1, 1);
            rs1 += __shfl_xor_sync(0xffffffffu, rs1, 2);
            l0 = l0 * f0 + rs0;
            l1 = l1 * f1 + rs1;
#pragma unroll
            for (int dt = 0; dt < 8; dt++) {
                oacc[dt][0] *= f0; oacc[dt][1] *= f0;
                oacc[dt][2] *= f1; oacc[dt][3] *= f1;
            }
            // ---- O += P @ V (P repacked reg-only into A frags, hi/lo)
#pragma unroll
            for (int ks = 0; ks < 4; ks++) {
                uint32_t pah[4], pal[4];
                pack_hilo(sacc[2*ks][0],   sacc[2*ks][1],   pah[0], pal[0]);
                pack_hilo(sacc[2*ks][2],   sacc[2*ks][3],   pah[1], pal[1]);
                pack_hilo(sacc[2*ks+1][0], sacc[2*ks+1][1], pah[2], pal[2]);
                pack_hilo(sacc[2*ks+1][2], sacc[2*ks+1][3], pah[3], pal[3]);
#pragma unroll
                for (int dp = 0; dp < 4; dp++) {
                    int row = dp * 16 + (lane & 15);
                    int u = ks * 2 + (lane >> 4); int ph = u ^ (row & 7);
                    uint32_t o = row * 128 + ph * 16;
                    uint32_t th[4], tl[4];
                    ldsm4(th, kb + 16384 + o);
                    ldsm4(tl, kb + 24576 + o);
                    uint32_t beh[2] = {th[0], th[2]}, boh[2] = {th[1], th[3]};
                    uint32_t bel[2] = {tl[0], tl[2]}, bol[2] = {tl[1], tl[3]};
                    mma16816(oacc[2*dp],   pah, beh);
                    mma16816(oacc[2*dp],   pah, bel);
                    mma16816(oacc[2*dp],   pal, beh);
                    mma16816(oacc[2*dp+1], pah, boh);
                    mma16816(oacc[2*dp+1], pah, bol);
                    mma16816(oacc[2*dp+1], pal, boh);
                }
            }
        }
        __syncthreads();
    }

    // ---- epilogue: normalize, split hi/lo, write out-proj A operand
    float i0 = 1.f / l0, i1 = 1.f / l1;
#pragma unroll
    for (int dt = 0; dt < 8; dt++) {
        int c = h * Dh + dt * 8 + (lane & 3) * 2;
        uint32_t hh, ll;
        pack_hilo(oacc[dt][0] * i0, oacc[dt][1] * i0, hh, ll);
        size_t off = ((size_t)b * Ts + rg0) * Cc + c;
        *(uint32_t*)(g_a_h + off) = hh;
        *(uint32_t*)(g_a_l + off) = ll;
        pack_hilo(oacc[dt][2] * i1, oacc[dt][3] * i1, hh, ll);
        off = ((size_t)b * Ts + rg0 + 8) * Cc + c;
        *(uint32_t*)(g_a_h + off) = hh;
        *(uint32_t*)(g_a_l + off) = ll;
    }
}

// ---------------------------------------------------------------------------
// Launch (graph-capturable: kernels only)
// ---------------------------------------------------------------------------
extern "C" void kernel_launch(void* const* d_in, const int* in_sizes, int n_in,
                              void* d_out, int out_size)
{
    const float* x     = (const float*)d_in[0];
    const float* w_qkv = (const float*)d_in[1];
    const float* b_qkv = (const float*)d_in[2];
    const float* w_out = (const float*)d_in[3];
    const float* b_out = (const float*)d_in[4];
    float* out = (float*)d_out;

    float* qkv_ptr;
    __half *xh, *xl, *wqh, *wql, *woh, *wol, *ah, *al;
    cudaGetSymbolAddress((void**)&qkv_ptr, g_qkv);
    cudaGetSymbolAddress((void**)&xh,  g_x_h);  cudaGetSymbolAddress((void**)&xl,  g_x_l);
    cudaGetSymbolAddress((void**)&wqh, g_wq_h); cudaGetSymbolAddress((void**)&wql, g_wq_l);
    cudaGetSymbolAddress((void**)&woh, g_wo_h); cudaGetSymbolAddress((void**)&wol, g_wo_l);
    cudaGetSymbolAddress((void**)&ah,  g_a_h);  cudaGetSymbolAddress((void**)&al,  g_a_l);

    cudaFuncSetAttribute(gemm_hmma, cudaFuncAttributeMaxDynamicSharedMemorySize, GEMM_SMEM);
    cudaFuncSetAttribute(flash_hmma, cudaFuncAttributeMaxDynamicSharedMemorySize, ATT_SMEM);

    // 0) operand conversion
    conv_A<<<(int)(((size_t)Mtot * Kd / 8) / 256), 256>>>(x, xh, xl);
    conv_B<<<dim3(Nqkv / 256, Kd / 8), 256>>>(w_qkv, wqh, wql, Nqkv);
    conv_B<<<dim3(Cc / 256, Kd / 8), 256>>>(w_out, woh, wol, Cc);

    // 1) QKV projection (HMMA)
    gemm_hmma<<<dim3(Nqkv / 128, Mtot / 128), 256, GEMM_SMEM>>>(
        xh, xl, wqh, wql, b_qkv, qkv_ptr, Nqkv);

    // 2) per-head hi/lo conversion + V transpose
    conv_qkv<<<dim3(Ts / 64, Hh, Bb), 256>>>();

    // 3) causal flash attention (HMMA), writes g_a_h/g_a_l directly
    flash_hmma<<<dim3(Ts / 128, Hh, Bb), 256, ATT_SMEM>>>();

    // 4) output projection (HMMA)
    gemm_hmma<<<dim3(Cc / 128, Mtot / 128), 256, GEMM_SMEM>>>(
        ah, al, woh, wol, b_out, out, Cc);
}

// round 10
// speedup vs baseline: 2.5370x; 1.0796x over previous
#include <cuda_runtime.h>
#include <cuda_fp16.h>
#include <cstdint>

// ---------------- problem constants ----------------
constexpr int Bb   = 4;
constexpr int Ts   = 2048;
constexpr int Cc   = 1024;
constexpr int Hh   = 16;
constexpr int Dh   = 64;
constexpr int Mtot = Bb * Ts;      // 8192
constexpr int Nqkv = 3 * Cc;       // 3072
constexpr int Kd   = Cc;           // 1024

// ---------------- scratch (device globals) ----------------
__device__ float g_qkv[(size_t)Mtot * Nqkv];
__device__ __align__(1024) __half g_x_h[(size_t)Mtot * Kd];   // x hi  [M][K]
__device__ __align__(1024) __half g_x_l[(size_t)Mtot * Kd];
__device__ __align__(1024) __half g_wq_h[(size_t)Nqkv * Kd];  // w_qkv^T hi [N][K]
__device__ __align__(1024) __half g_wq_l[(size_t)Nqkv * Kd];
__device__ __align__(1024) __half g_wo_h[(size_t)Cc * Kd];    // w_out^T hi [N][K]
__device__ __align__(1024) __half g_wo_l[(size_t)Cc * Kd];
__device__ __align__(1024) __half g_a_h[(size_t)Mtot * Kd];   // attn out hi [M][K]
__device__ __align__(1024) __half g_a_l[(size_t)Mtot * Kd];
// attention operands, per-head layouts
__device__ __align__(1024) __half g_q_h[(size_t)Bb * Hh * Ts * Dh];   // [b,h,t,d] (pre-scaled)
__device__ __align__(1024) __half g_q_l[(size_t)Bb * Hh * Ts * Dh];
__device__ __align__(1024) __half g_k_h[(size_t)Bb * Hh * Ts * Dh];   // [b,h,t,d]
__device__ __align__(1024) __half g_k_l[(size_t)Bb * Hh * Ts * Dh];
__device__ __align__(1024) __half g_vt_h[(size_t)Bb * Hh * Dh * Ts];  // [b,h,d,t]
__device__ __align__(1024) __half g_vt_l[(size_t)Bb * Hh * Dh * Ts];

// ---------------- PTX helpers (sm_80-level, compile for compute_103) --------
__device__ __forceinline__ uint32_t smem_u32(const void* p) {
    uint32_t a;
    asm("{ .reg .u64 t; cvta.to.shared.u64 t, %1; cvt.u32.u64 %0, t; }" : "=r"(a) : "l"(p));
    return a;
}
__device__ __forceinline__ void cpa16(uint32_t dst, const void* src) {
    asm volatile("cp.async.cg.shared.global [%0], [%1], 16;" :: "r"(dst), "l"(src));
}
__device__ __forceinline__ void cp_commit() {
    asm volatile("cp.async.commit_group;" ::: "memory");
}
template<int n>
__device__ __forceinline__ void cp_wait() {
    asm volatile("cp.async.wait_group %0;" :: "n"(n) : "memory");
}
__device__ __forceinline__ void ldsm4(uint32_t* r, uint32_t addr) {
    asm volatile("ldmatrix.sync.aligned.m8n8.x4.shared.b16 {%0,%1,%2,%3}, [%4];"
                 : "=r"(r[0]), "=r"(r[1]), "=r"(r[2]), "=r"(r[3]) : "r"(addr));
}
__device__ __forceinline__ void mma16816(float* d, const uint32_t* a, const uint32_t* b) {
    asm volatile(
        "mma.sync.aligned.m16n8k16.row.col.f32.f16.f16.f32 "
        "{%0,%1,%2,%3}, {%4,%5,%6,%7}, {%8,%9}, {%0,%1,%2,%3};"
        : "+f"(d[0]), "+f"(d[1]), "+f"(d[2]), "+f"(d[3])
        : "r"(a[0]), "r"(a[1]), "r"(a[2]), "r"(a[3]), "r"(b[0]), "r"(b[1]));
}
__device__ __forceinline__ void pack_hilo(float x, float y, uint32_t& h, uint32_t& l) {
    __half2 hh = __floats2half2_rn(x, y);
    float2 hf = __half22float2(hh);
    __half2 ll = __floats2half2_rn(x - hf.x, y - hf.y);
    h = *(uint32_t*)&hh;
    l = *(uint32_t*)&ll;
}

// ---------------------------------------------------------------------------
// conv_A: fp32 [rows,1024] -> hi/lo fp16 row-major (8 elems/thread)
// ---------------------------------------------------------------------------
__global__ __launch_bounds__(256)
void conv_A(const float* __restrict__ src, __half* __restrict__ dh, __half* __restrict__ dl)
{
    size_t u = (size_t)blockIdx.x * 256 + threadIdx.x;
    const float4* p = (const float4*)(src + u * 8);
    float4 f0 = p[0], f1 = p[1];
    float f[8] = {f0.x, f0.y, f0.z, f0.w, f1.x, f1.y, f1.z, f1.w};
    union { __half h[8]; uint4 v; } H, L;
#pragma unroll
    for (int j = 0; j < 8; j++) {
        __half hi = __float2half_rn(f[j]);
        H.h[j] = hi;
        L.h[j] = __float2half_rn(f[j] - __half2float(hi));
    }
    *(uint4*)(dh + u * 8) = H.v;
    *(uint4*)(dl + u * 8) = L.v;
}

// conv_B: fp32 weight [K,N] -> transposed [N][K] hi/lo
__global__ __launch_bounds__(256)
void conv_B(const float* __restrict__ w, __half* __restrict__ dh, __half* __restrict__ dl, int N)
{
    int n  = blockIdx.x * 256 + threadIdx.x;
    int k0 = blockIdx.y * 8;
    union { __half h[8]; uint4 v; } H, L;
#pragma unroll
    for (int j = 0; j < 8; j++) {
        float f = w[(size_t)(k0 + j) * N + n];
        __half hi = __float2half_rn(f);
        H.h[j] = hi;
        L.h[j] = __float2half_rn(f - __half2float(hi));
    }
    *(uint4*)(dh + (size_t)n * Kd + k0) = H.v;
    *(uint4*)(dl + (size_t)n * Kd + k0) = L.v;
}

// ---------------------------------------------------------------------------
// conv_qkv: g_qkv fp32 -> Q(hi/lo, pre-scaled) [b,h,t,d], K(hi/lo) [b,h,t,d],
//           V^T(hi/lo) [b,h,d,t].  grid (Ts/64, Hh, Bb), 256 thr.
// ---------------------------------------------------------------------------
__global__ __launch_bounds__(256)
void conv_qkv()
{
    __shared__ float vs[64][65];
    const int b = blockIdx.z, h = blockIdx.y, t0 = blockIdx.x * 64;
    const int tid = threadIdx.x;
    const int tl = tid >> 2;
    const int d0 = (tid & 3) * 16;
    const float* src = g_qkv + ((size_t)b * Ts + t0 + tl) * Nqkv + h * Dh + d0;
    const size_t qk_off = ((size_t)(b * Hh + h) * Ts + t0 + tl) * Dh + d0;

    union { __half hh[16]; uint4 v[2]; } QH_, QL_, KH_, KL_;
#pragma unroll
    for (int j = 0; j < 16; j++) {
        float q = src[j] * 0.125f;
        __half qh = __float2half_rn(q);
        QH_.hh[j] = qh;
        QL_.hh[j] = __float2half_rn(q - __half2float(qh));
        float k = src[Cc + j];
        __half kh = __float2half_rn(k);
        KH_.hh[j] = kh;
        KL_.hh[j] = __float2half_rn(k - __half2float(kh));
        vs[tl][d0 + j] = src[2 * Cc + j];
    }
    *(uint4*)(g_q_h + qk_off) = QH_.v[0]; *(uint4*)(g_q_h + qk_off + 8) = QH_.v[1];
    *(uint4*)(g_q_l + qk_off) = QL_.v[0]; *(uint4*)(g_q_l + qk_off + 8) = QL_.v[1];
    *(uint4*)(g_k_h + qk_off) = KH_.v[0]; *(uint4*)(g_k_h + qk_off + 8) = KH_.v[1];
    *(uint4*)(g_k_l + qk_off) = KL_.v[0]; *(uint4*)(g_k_l + qk_off + 8) = KL_.v[1];
    __syncthreads();

    const int d  = tid >> 2;
    const int tg = (tid & 3) * 16;
    union { __half hh[16]; uint4 v[2]; } VH_, VL_;
#pragma unroll
    for (int j = 0; j < 16; j++) {
        float f = vs[tg + j][d];
        __half hi = __float2half_rn(f);
        VH_.hh[j] = hi;
        VL_.hh[j] = __float2half_rn(f - __half2float(hi));
    }
    size_t vt_off = ((size_t)(b * Hh + h) * Dh + d) * Ts + t0 + tg;
    *(uint4*)(g_vt_h + vt_off) = VH_.v[0]; *(uint4*)(g_vt_h + vt_off + 8) = VH_.v[1];
    *(uint4*)(g_vt_l + vt_off) = VL_.v[0]; *(uint4*)(g_vt_l + vt_off + 8) = VL_.v[1];
}

// ---------------------------------------------------------------------------
// HMMA GEMM v2: C = (Ah+Al) @ (Bh+Bl)^T + bias.
// 128x128 block tile, BK=32, 3-stage cp.async, 2 blocks/SM (96 KB smem).
// Smem rows are 64 B (4 x 16B units); swizzle u_phys = u ^ ((row>>1)&3)
// keeps ldmatrix conflict-free (granule = 4*(r&1) + u^((r>>1)&3) covers all 8).
// ---------------------------------------------------------------------------
constexpr int BK2      = 32;
constexpr int T2_BYTES = 128 * BK2 * 2;     // 8 KB per operand tile
constexpr int S2_BYTES = 4 * T2_BYTES;      // 32 KB per stage (Ah, Al, Bh, Bl)
constexpr int NST      = 3;
constexpr int GEMM_SMEM = NST * S2_BYTES;   // 98304
constexpr int NCH2     = Kd / BK2;          // 32 chunks

__global__ __launch_bounds__(256, 2)
void gemm_hmma(const __half* __restrict__ Ah, const __half* __restrict__ Al,
               const __half* __restrict__ Bh, const __half* __restrict__ Bl,
               const float* __restrict__ bias, float* __restrict__ C, int N)
{
    extern __shared__ char smem_raw[];
    const uint32_t sbase = smem_u32(smem_raw);

    const int tid  = threadIdx.x;
    const int lane = tid & 31;
    const int wid  = tid >> 5;
    const int wm   = wid >> 2;          // 0..1  (M)
    const int wn   = wid & 3;           // 0..3  (N)
    const int bm   = blockIdx.y, bn = blockIdx.x;

    // cp.async mapping: thread t -> row r = t>>1, units u0, u0+1 (u0 = (t&1)*2)
    const int cr  = tid >> 1;
    const int cu0 = (tid & 1) * 2;
    const int csw = (cr >> 1) & 3;
    const __half* srcs[4] = {
        Ah + (size_t)(bm * 128 + cr) * Kd,
        Al + (size_t)(bm * 128 + cr) * Kd,
        Bh + (size_t)(bn * 128 + cr) * Kd,
        Bl + (size_t)(bn * 128 + cr) * Kd
    };
    const uint32_t dstrow = (uint32_t)cr * 64;

    auto load_stage = [&](int s, int ch) {
        uint32_t sb = sbase + s * S2_BYTES;
#pragma unroll
        for (int t = 0; t < 4; t++) {
            const __half* src = srcs[t] + ch * BK2;
            uint32_t tb = sb + t * T2_BYTES + dstrow;
#pragma unroll
            for (int j = 0; j < 2; j++) {
                int u = cu0 + j;
                cpa16(tb + ((u ^ csw) * 16), src + u * 8);
            }
        }
    };

    float acc[4][4][4];
#pragma unroll
    for (int i = 0; i < 4; i++)
#pragma unroll
        for (int j = 0; j < 4; j++)
#pragma unroll
            for (int k = 0; k < 4; k++) acc[i][j][k] = 0.f;

    // per-thread ldmatrix row bases (row = base + lane&15, k-unit = ks*2 + lane>>4)
    const int rA = lane & 15, kg = lane >> 4;
    uint32_t arow[4], brow[2];
    int asw[4], bsw[2];
#pragma unroll
    for (int mi = 0; mi < 4; mi++) {
        int r = wm * 64 + mi * 16 + rA;
        arow[mi] = (uint32_t)r * 64; asw[mi] = (r >> 1) & 3;
    }
#pragma unroll
    for (int np = 0; np < 2; np++) {
        int r = wn * 32 + np * 16 + rA;
        brow[np] = (uint32_t)r * 64; bsw[np] = (r >> 1) & 3;
    }

    load_stage(0, 0); cp_commit();
    load_stage(1, 1); cp_commit();

    for (int i = 0; i < NCH2; i++) {
        if (i + 2 < NCH2) { load_stage((i + 2) % NST, i + 2); cp_commit(); cp_wait<2>(); }
        else if (i + 1 < NCH2) { cp_wait<1>(); }
        else { cp_wait<0>(); }
        __syncthreads();

        uint32_t sb = sbase + (i % NST) * S2_BYTES;
#pragma unroll
        for (int ks = 0; ks < 2; ks++) {
            int kb = ks * 2 + kg;
            // B fragments first (held across the mi loop)
            uint32_t bh[4][2], bl[4][2];
#pragma unroll
            for (int np = 0; np < 2; np++) {
                uint32_t off = brow[np] + (uint32_t)((kb ^ bsw[np]) * 16);
                uint32_t t[4];
                ldsm4(t, sb + 2 * T2_BYTES + off);
                bh[2*np][0] = t[0]; bh[2*np+1][0] = t[1];
                bh[2*np][1] = t[2]; bh[2*np+1][1] = t[3];
                ldsm4(t, sb + 3 * T2_BYTES + off);
                bl[2*np][0] = t[0]; bl[2*np+1][0] = t[1];
                bl[2*np][1] = t[2]; bl[2*np+1][1] = t[3];
            }
            // stream A fragments per mi
#pragma unroll
            for (int mi = 0; mi < 4; mi++) {
                uint32_t off = arow[mi] + (uint32_t)((kb ^ asw[mi]) * 16);
                uint32_t ah[4], al[4];
                ldsm4(ah, sb + off);
                ldsm4(al, sb + T2_BYTES + off);
#pragma unroll
                for (int ni = 0; ni < 4; ni++) {
                    mma16816(acc[mi][ni], ah, bh[ni]);
                    mma16816(acc[mi][ni], ah, bl[ni]);
                    mma16816(acc[mi][ni], al, bh[ni]);
                }
            }
        }
        __syncthreads();
    }

    const int er = lane >> 2, ec = (lane & 3) * 2;
#pragma unroll
    for (int mi = 0; mi < 4; mi++) {
        size_t r0 = (size_t)bm * 128 + wm * 64 + mi * 16 + er;
#pragma unroll
        for (int ni = 0; ni < 4; ni++) {
            int c = bn * 128 + wn * 32 + ni * 8 + ec;
            float2 bv = *(const float2*)(bias + c);
            float2 o0 = { acc[mi][ni][0] + bv.x, acc[mi][ni][1] + bv.y };
            float2 o1 = { acc[mi][ni][2] + bv.x, acc[mi][ni][3] + bv.y };
            *(float2*)(C + r0 * N + c)       = o0;
            *(float2*)(C + (r0 + 8) * N + c) = o1;
        }
    }
}

// ---------------------------------------------------------------------------
// flash_hmma: causal flash attention on mma.sync (unchanged, known-good R9).
// ---------------------------------------------------------------------------
constexpr int ATT_SMEM = 32768 + 2 * 32768;  // 98304

__global__ __launch_bounds__(256, 1)
void flash_hmma()
{
    extern __shared__ char sm[];
    const uint32_t sb  = smem_u32(sm);
    const uint32_t QHs = sb, QLs = sb + 16384;

    const int tid = threadIdx.x, lane = tid & 31, wq = tid >> 5;
    const int qt = blockIdx.x, h = blockIdx.y, b = blockIdx.z;
    const int q0 = qt * 128;
    const int ktmax = 2 * qt + 1;

    const size_t bh = (size_t)(b * Hh + h);
    const __half* Qh = g_q_h + (bh * Ts + q0) * Dh;
    const __half* Ql = g_q_l + (bh * Ts + q0) * Dh;
    const __half* Kh = g_k_h + bh * Ts * Dh;
    const __half* Kl = g_k_l + bh * Ts * Dh;
    const __half* Vh = g_vt_h + bh * Dh * Ts;
    const __half* Vl = g_vt_l + bh * Dh * Ts;

    {
        int qr = tid >> 1, u0 = (tid & 1) * 4;
#pragma unroll
        for (int j = 0; j < 4; j++) {
            int u = u0 + j; int ph = u ^ (qr & 7);
            cpa16(QHs + qr * 128 + ph * 16, Qh + (size_t)qr * 64 + u * 8);
            cpa16(QLs + qr * 128 + ph * 16, Ql + (size_t)qr * 64 + u * 8);
        }
    }
    const int kr = tid >> 2, ku0 = (tid & 3) * 2;
    auto load_kv = [&](int s, int kt) {
        uint32_t base = sb + 32768 + s * 32768;
        int k0 = kt * 64;
#pragma unroll
        for (int j = 0; j < 2; j++) {
            int u = ku0 + j; int ph = u ^ (kr & 7);
            uint32_t o = kr * 128 + ph * 16;
            cpa16(base + o,         Kh + (size_t)(k0 + kr) * 64 + u * 8);
            cpa16(base + 8192 + o,  Kl + (size_t)(k0 + kr) * 64 + u * 8);
            cpa16(base + 16384 + o, Vh + (size_t)kr * Ts + k0 + u * 8);
            cpa16(base + 24576 + o, Vl + (size_t)kr * Ts + k0 + u * 8);
        }
    };
    load_kv(0, 0);
    cp_commit();
    load_kv(1, 1);
    cp_commit();
    cp_wait<1>();
    __syncthreads();

    uint32_t qfh[4][4], qfl[4][4];
    {
        int row = wq * 16 + (lane & 15);
#pragma unroll
        for (int ks = 0; ks < 4; ks++) {
            int u = ks * 2 + (lane >> 4); int ph = u ^ (row & 7);
            uint32_t o = row * 128 + ph * 16;
            ldsm4(qfh[ks], QHs + o);
            ldsm4(qfl[ks], QLs + o);
        }
    }

    float m0 = -1e30f, m1 = -1e30f, l0 = 0.f, l1 = 0.f;
    float oacc[8][4];
#pragma unroll
    for (int i = 0; i < 8; i++)
#pragma unroll
        for (int j = 0; j < 4; j++) oacc[i][j] = 0.f;

    const int rg0 = q0 + wq * 16 + (lane >> 2);

    for (int kt = 0; kt <= ktmax; kt++) {
        if (kt > 0) {
            if (kt + 1 <= ktmax) { load_kv((kt + 1) & 1, kt + 1); cp_commit(); cp_wait<1>(); }
            else                 { cp_wait<0>(); }
            __syncthreads();
        }
        const uint32_t kb = sb + 32768 + (kt & 1) * 32768;
        const int k0 = kt * 64;

        if (k0 <= q0 + wq * 16 + 15) {
            float sacc[8][4];
#pragma unroll
            for (int i = 0; i < 8; i++)
#pragma unroll
                for (int j = 0; j < 4; j++) sacc[i][j] = 0.f;

#pragma unroll
            for (int ks = 0; ks < 4; ks++) {
#pragma unroll
                for (int np = 0; np < 4; np++) {
                    int row = np * 16 + (lane & 15);
                    int u = ks * 2 + (lane >> 4); int ph = u ^ (row & 7);
                    uint32_t o = row * 128 + ph * 16;
                    uint32_t th[4], tl[4];
                    ldsm4(th, kb + o);
                    ldsm4(tl, kb + 8192 + o);
                    uint32_t beh[2] = {th[0], th[2]}, boh[2] = {th[1], th[3]};
                    uint32_t bel[2] = {tl[0], tl[2]}, bol[2] = {tl[1], tl[3]};
                    mma16816(sacc[2*np],   qfh[ks], beh);
                    mma16816(sacc[2*np],   qfh[ks], bel);
                    mma16816(sacc[2*np],   qfl[ks], beh);
                    mma16816(sacc[2*np+1], qfh[ks], boh);
                    mma16816(sacc[2*np+1], qfh[ks], bol);
                    mma16816(sacc[2*np+1], qfl[ks], boh);
                }
            }
            if (k0 + 63 > q0 + wq * 16) {
#pragma unroll
                for (int nt = 0; nt < 8; nt++) {
                    int cg = k0 + nt * 8 + (lane & 3) * 2;
                    if (cg     > rg0)     sacc[nt][0] = -1e30f;
                    if (cg + 1 > rg0)     sacc[nt][1] = -1e30f;
                    if (cg     > rg0 + 8) sacc[nt][2] = -1e30f;
                    if (cg + 1 > rg0 + 8) sacc[nt][3] = -1e30f;
                }
            }
            float mx0 = -1e30f, mx1 = -1e30f;
#pragma unroll
            for (int nt = 0; nt < 8; nt++) {
                mx0 = fmaxf(mx0, fmaxf(sacc[nt][0], sacc[nt][1]));
                mx1 = fmaxf(mx1, fmaxf(sacc[nt][2], sacc[nt][3]));
            }
            mx0 = fmaxf(mx0, __shfl_xor_sync(0xffffffffu, mx0, 1));
            mx0 = fmaxf(mx0, __shfl_xor_sync(0xffffffffu, mx0, 2));
            mx1 = fmaxf(mx1, __shfl_xor_sync(0xffffffffu, mx1, 1));
            mx1 = fmaxf(mx1, __shfl_xor_sync(0xffffffffu, mx1, 2));
            float mn0 = fmaxf(m0, mx0), mn1 = fmaxf(m1, mx1);
            float f0 = __expf(m0 - mn0), f1 = __expf(m1 - mn1);
            m0 = mn0; m1 = mn1;
            float rs0 = 0.f, rs1 = 0.f;
#pragma unroll
            for (int nt = 0; nt < 8; nt++) {
                sacc[nt][0] = __expf(sacc[nt][0] - mn0); rs0 += sacc[nt][0];
                sacc[nt][1] = __expf(sacc[nt][1] - mn0); rs0 += sacc[nt][1];
                sacc[nt][2] = __expf(sacc[nt][2] - mn1); rs1 += sacc[nt][2];
                sacc[nt][3] = __expf(sacc[nt][3] - mn1); rs1 += sacc[nt][3];
            }
            rs0 += __shfl_xor_sync(0xffffffffu, rs0, 1);
            rs0 += __shfl_xor_sync(0xffffffffu, rs0, 2);
            rs1 += __shfl_xor_sync(0xffffffffu, rs1, 1);
            rs1 += __shfl_xor_sync(0xffffffffu, rs1, 2);
            l0 = l0 * f0 + rs0;
            l1 = l1 * f1 + rs1;
#pragma unroll
            for (int dt = 0; dt < 8; dt++) {
                oacc[dt][0] *= f0; oacc[dt][1] *= f0;
                oacc[dt][2] *= f1; oacc[dt][3] *= f1;
            }
#pragma unroll
            for (int ks = 0; ks < 4; ks++) {
                uint32_t pah[4], pal[4];
                pack_hilo(sacc[2*ks][0],   sacc[2*ks][1],   pah[0], pal[0]);
                pack_hilo(sacc[2*ks][2],   sacc[2*ks][3],   pah[1], pal[1]);
                pack_hilo(sacc[2*ks+1][0], sacc[2*ks+1][1], pah[2], pal[2]);
                pack_hilo(sacc[2*ks+1][2], sacc[2*ks+1][3], pah[3], pal[3]);
#pragma unroll
                for (int dp = 0; dp < 4; dp++) {
                    int row = dp * 16 + (lane & 15);
                    int u = ks * 2 + (lane >> 4); int ph = u ^ (row & 7);
                    uint32_t o = row * 128 + ph * 16;
                    uint32_t th[4], tl[4];
                    ldsm4(th, kb + 16384 + o);
                    ldsm4(tl, kb + 24576 + o);
                    uint32_t beh[2] = {th[0], th[2]}, boh[2] = {th[1], th[3]};
                    uint32_t bel[2] = {tl[0], tl[2]}, bol[2] = {tl[1], tl[3]};
                    mma16816(oacc[2*dp],   pah, beh);
                    mma16816(oacc[2*dp],   pah, bel);
                    mma16816(oacc[2*dp],   pal, beh);
                    mma16816(oacc[2*dp+1], pah, boh);
                    mma16816(oacc[2*dp+1], pah, bol);
                    mma16816(oacc[2*dp+1], pal, boh);
                }
            }
        }
        __syncthreads();
    }

    float i0 = 1.f / l0, i1 = 1.f / l1;
#pragma unroll
    for (int dt = 0; dt < 8; dt++) {
        int c = h * Dh + dt * 8 + (lane & 3) * 2;
        uint32_t hh, ll;
        pack_hilo(oacc[dt][0] * i0, oacc[dt][1] * i0, hh, ll);
        size_t off = ((size_t)b * Ts + rg0) * Cc + c;
        *(uint32_t*)(g_a_h + off) = hh;
        *(uint32_t*)(g_a_l + off) = ll;
        pack_hilo(oacc[dt][2] * i1, oacc[dt][3] * i1, hh, ll);
        off = ((size_t)b * Ts + rg0 + 8) * Cc + c;
        *(uint32_t*)(g_a_h + off) = hh;
        *(uint32_t*)(g_a_l + off) = ll;
    }
}

// ---------------------------------------------------------------------------
// Launch (graph-capturable: kernels only)
// ---------------------------------------------------------------------------
extern "C" void kernel_launch(void* const* d_in, const int* in_sizes, int n_in,
                              void* d_out, int out_size)
{
    const float* x     = (const float*)d_in[0];
    const float* w_qkv = (const float*)d_in[1];
    const float* b_qkv = (const float*)d_in[2];
    const float* w_out = (const float*)d_in[3];
    const float* b_out = (const float*)d_in[4];
    float* out = (float*)d_out;

    float* qkv_ptr;
    __half *xh, *xl, *wqh, *wql, *woh, *wol, *ah, *al;
    cudaGetSymbolAddress((void**)&qkv_ptr, g_qkv);
    cudaGetSymbolAddress((void**)&xh,  g_x_h);  cudaGetSymbolAddress((void**)&xl,  g_x_l);
    cudaGetSymbolAddress((void**)&wqh, g_wq_h); cudaGetSymbolAddress((void**)&wql, g_wq_l);
    cudaGetSymbolAddress((void**)&woh, g_wo_h); cudaGetSymbolAddress((void**)&wol, g_wo_l);
    cudaGetSymbolAddress((void**)&ah,  g_a_h);  cudaGetSymbolAddress((void**)&al,  g_a_l);

    cudaFuncSetAttribute(gemm_hmma, cudaFuncAttributeMaxDynamicSharedMemorySize, GEMM_SMEM);
    cudaFuncSetAttribute(flash_hmma, cudaFuncAttributeMaxDynamicSharedMemorySize, ATT_SMEM);

    // 0) operand conversion
    conv_A<<<(int)(((size_t)Mtot * Kd / 8) / 256), 256>>>(x, xh, xl);
    conv_B<<<dim3(Nqkv / 256, Kd / 8), 256>>>(w_qkv, wqh, wql, Nqkv);
    conv_B<<<dim3(Cc / 256, Kd / 8), 256>>>(w_out, woh, wol, Cc);

    // 1) QKV projection (HMMA)
    gemm_hmma<<<dim3(Nqkv / 128, Mtot / 128), 256, GEMM_SMEM>>>(
        xh, xl, wqh, wql, b_qkv, qkv_ptr, Nqkv);

    // 2) per-head hi/lo conversion + V transpose
    conv_qkv<<<dim3(Ts / 64, Hh, Bb), 256>>>();

    // 3) causal flash attention (HMMA), writes g_a_h/g_a_l directly
    flash_hmma<<<dim3(Ts / 128, Hh, Bb), 256, ATT_SMEM>>>();

    // 4) output projection (HMMA)
    gemm_hmma<<<dim3(Cc / 128, Mtot / 128), 256, GEMM_SMEM>>>(
        ah, al, woh, wol, b_out, out, Cc);
}